// round 2
// baseline (speedup 1.0000x reference)
#include <cuda_runtime.h>

#define Bn  16
#define Qn  64
#define Kn  1024
#define Dn  256
#define Hn  128
#define DVn 256

// Scratch (device globals; no allocation allowed in kernel_launch)
__device__ float g_kproj[Bn * Kn * Hn];   // 8 MB
__device__ float g_qproj[Bn * Qn * Hn];   // 0.5 MB
__device__ float g_scores[Bn * Qn * Kn];  // 4 MB (scores, then attn in-place)

__device__ __forceinline__ float fast_tanh(float x) {
    float y;
    asm("tanh.approx.f32 %0, %1;" : "=f"(y) : "f"(x));
    return y;
}

// ---------------------------------------------------------------------------
// P[b, n, h] = X[b, n, :Dn] @ W[Dn, Hn]
// Tile: 64 rows x 128 cols per CTA, 256 threads, each thread 8x4 outputs.
// ---------------------------------------------------------------------------
template <bool TO_K>
__global__ void proj_kernel(const float* __restrict__ X,
                            const float* __restrict__ W, int N) {
    const int b    = blockIdx.y;
    const int row0 = blockIdx.x * 64;
    const int tid  = threadIdx.x;
    const int tx   = tid & 31;   // h-group (4 cols)
    const int ty   = tid >> 5;   // row-group (8 rows)

    __shared__ __align__(16) float sX[64][33];
    __shared__ __align__(16) float sW[32][132];

    float acc[8][4];
#pragma unroll
    for (int i = 0; i < 8; i++) {
        acc[i][0] = acc[i][1] = acc[i][2] = acc[i][3] = 0.f;
    }

    const float* Xb = X + ((size_t)b * N + row0) * Dn;

    for (int d0 = 0; d0 < Dn; d0 += 32) {
        // X tile: 64 x 32 (coalesced: consecutive tid -> consecutive d)
#pragma unroll
        for (int i = 0; i < 8; i++) {
            int j = tid + i * 256;
            int r = j >> 5, d = j & 31;
            sX[r][d] = Xb[r * Dn + d0 + d];
        }
        // W tile: 32 x 128
#pragma unroll
        for (int i = 0; i < 16; i++) {
            int j  = tid + i * 256;
            int dd = j >> 7, h = j & 127;
            sW[dd][h] = W[(d0 + dd) * Hn + h];
        }
        __syncthreads();

#pragma unroll 8
        for (int dd = 0; dd < 32; dd++) {
            float4 w = *(const float4*)&sW[dd][tx * 4];
#pragma unroll
            for (int i = 0; i < 8; i++) {
                float x = sX[ty * 8 + i][dd];  // broadcast within warp
                acc[i][0] += x * w.x;
                acc[i][1] += x * w.y;
                acc[i][2] += x * w.z;
                acc[i][3] += x * w.w;
            }
        }
        __syncthreads();
    }

    float* P  = TO_K ? g_kproj : g_qproj;
    float* Pb = P + ((size_t)b * N + row0) * Hn;
#pragma unroll
    for (int i = 0; i < 8; i++) {
        *(float4*)&Pb[(ty * 8 + i) * Hn + tx * 4] =
            make_float4(acc[i][0], acc[i][1], acc[i][2], acc[i][3]);
    }
}

// ---------------------------------------------------------------------------
// scores[b, q, k] = sum_h wv[h] * tanh(qproj[b,q,h] + kproj[b,k,h])
// CTA = (k-tile 32, q-half 32, b). smem: 32 q rows + 32 padded k rows = 33.4KB
// (fits the 48KB static limit; the R1 version with all 64 q rows did not).
// Thread: kk = tid%32 (one k), 4 consecutive q's -> 4 accumulators.
// ---------------------------------------------------------------------------
__global__ void scores_kernel(const float* __restrict__ wv) {
    const int b   = blockIdx.z;
    const int qh  = blockIdx.y * 32;
    const int k0  = blockIdx.x * 32;
    const int tid = threadIdx.x;

    __shared__ __align__(16) float sQ[32][Hn];   // 16 KB
    __shared__ __align__(16) float sK[32][132];  // 16.9 KB padded rows
    __shared__ __align__(16) float sWv[Hn];

    // load qproj half-tile: 32 rows x 128 = 1024 float4
    {
        const float4* src =
            (const float4*)(g_qproj + ((size_t)b * Qn + qh) * Hn);
        float4* dst = (float4*)&sQ[0][0];
#pragma unroll
        for (int i = 0; i < 4; i++) {
            int j = tid + i * 256;
            dst[j] = src[j];
        }
    }
    // load kproj tile: 32 rows x 128 = 1024 float4, into padded rows
    {
        const float4* src =
            (const float4*)(g_kproj + ((size_t)b * Kn + k0) * Hn);
#pragma unroll
        for (int i = 0; i < 4; i++) {
            int j   = tid + i * 256;
            int row = j >> 5;            // 32 float4 per logical row
            int c4  = j & 31;
            *(float4*)&sK[row][c4 * 4] = src[j];
        }
    }
    if (tid < Hn) sWv[tid] = wv[tid];
    __syncthreads();

    const int kk = tid & 31;
    const int q0 = (tid >> 5) * 4;   // 8 groups x 4 q = 32 q
    float sc[4];
    sc[0] = sc[1] = sc[2] = sc[3] = 0.f;

#pragma unroll 4
    for (int h = 0; h < Hn; h += 4) {
        float4 kv = *(const float4*)&sK[kk][h];
        float4 w4 = *(const float4*)&sWv[h];
#pragma unroll
        for (int qi = 0; qi < 4; qi++) {
            float4 qv = *(const float4*)&sQ[q0 + qi][h];  // broadcast
            sc[qi] += w4.x * fast_tanh(qv.x + kv.x);
            sc[qi] += w4.y * fast_tanh(qv.y + kv.y);
            sc[qi] += w4.z * fast_tanh(qv.z + kv.z);
            sc[qi] += w4.w * fast_tanh(qv.w + kv.w);
        }
    }

    float* srow = g_scores + ((size_t)b * Qn + qh) * Kn + k0 + kk;
#pragma unroll
    for (int qi = 0; qi < 4; qi++) {
        srow[(size_t)(q0 + qi) * Kn] = sc[qi];
    }
}

// ---------------------------------------------------------------------------
// Masked softmax over K=1024, in place in g_scores.
// CTA = (q, b), 256 threads, float4 per thread.
// Reference semantics: invalid (k >= vlen) -> -1e6 before softmax.
// ---------------------------------------------------------------------------
__global__ void softmax_kernel(const int* __restrict__ vlen) {
    const int b   = blockIdx.y;
    const int q   = blockIdx.x;
    const int tid = threadIdx.x;

    float* row   = g_scores + ((size_t)b * Qn + q) * Kn;
    const int vl = vlen[b];

    float4 s      = ((const float4*)row)[tid];
    const int kb  = tid * 4;
    if (kb + 0 >= vl) s.x = -1e6f;
    if (kb + 1 >= vl) s.y = -1e6f;
    if (kb + 2 >= vl) s.z = -1e6f;
    if (kb + 3 >= vl) s.w = -1e6f;

    __shared__ float redm[8];
    __shared__ float reds[8];

    float m = fmaxf(fmaxf(s.x, s.y), fmaxf(s.z, s.w));
#pragma unroll
    for (int o = 16; o; o >>= 1) m = fmaxf(m, __shfl_xor_sync(0xffffffffu, m, o));
    if ((tid & 31) == 0) redm[tid >> 5] = m;
    __syncthreads();
    float M = redm[0];
#pragma unroll
    for (int i = 1; i < 8; i++) M = fmaxf(M, redm[i]);

    float e0 = __expf(s.x - M);
    float e1 = __expf(s.y - M);
    float e2 = __expf(s.z - M);
    float e3 = __expf(s.w - M);

    float t = (e0 + e1) + (e2 + e3);
#pragma unroll
    for (int o = 16; o; o >>= 1) t += __shfl_xor_sync(0xffffffffu, t, o);
    if ((tid & 31) == 0) reds[tid >> 5] = t;
    __syncthreads();
    float S = reds[0];
#pragma unroll
    for (int i = 1; i < 8; i++) S += reds[i];

    float inv = 1.0f / S;
    ((float4*)row)[tid] = make_float4(e0 * inv, e1 * inv, e2 * inv, e3 * inv);
}

// ---------------------------------------------------------------------------
// out[b, q, d] = sum_k attn[b,q,k] * values[b,k,d]
// CTA = (8-q group, b), 256 threads.
// Thread (ks = tid/64 in 0..3, c = tid%64): k stride 4, 4 dv cols (float4),
// all 8 q's. Cross-ks reduction through smem. k loop cut at vlen
// (attn beyond vlen is exactly 0: exp(-1e6 - max) underflows).
// ---------------------------------------------------------------------------
__global__ void av_kernel(const float* __restrict__ V,
                          const int* __restrict__ vlen,
                          float* __restrict__ out) {
    const int b   = blockIdx.y;
    const int q0  = blockIdx.x * 8;
    const int tid = threadIdx.x;
    const int ks  = tid >> 6;  // 0..3
    const int c   = tid & 63;  // float4 column group
    const int vl  = vlen[b];

    __shared__ __align__(16) float sA[8][128];   // 4 KB attn chunk
    __shared__ __align__(16) float sR[4][2048];  // 32 KB reduction

    float acc[8][4];
#pragma unroll
    for (int i = 0; i < 8; i++) {
        acc[i][0] = acc[i][1] = acc[i][2] = acc[i][3] = 0.f;
    }

    const float* Vb = V + (size_t)b * Kn * DVn;
    const float* Ab = g_scores + ((size_t)b * Qn + q0) * Kn;

    for (int k0 = 0; k0 < vl; k0 += 128) {
        // stage attn chunk: 8 q x 128 k
#pragma unroll
        for (int i = 0; i < 4; i++) {
            int j  = tid + i * 256;
            int qq = j >> 7, kk = j & 127;
            sA[qq][kk] = Ab[(size_t)qq * Kn + k0 + kk];
        }
        __syncthreads();

#pragma unroll 8
        for (int jj = 0; jj < 32; jj++) {
            int k    = ks + jj * 4;
            float4 v = *(const float4*)&Vb[(size_t)(k0 + k) * DVn + c * 4];
#pragma unroll
            for (int qi = 0; qi < 8; qi++) {
                float a = sA[qi][k];  // broadcast within warp
                acc[qi][0] += a * v.x;
                acc[qi][1] += a * v.y;
                acc[qi][2] += a * v.z;
                acc[qi][3] += a * v.w;
            }
        }
        __syncthreads();
    }

    // reduce the 4 k-splits
#pragma unroll
    for (int qi = 0; qi < 8; qi++) {
        *(float4*)&sR[ks][qi * 256 + c * 4] =
            make_float4(acc[qi][0], acc[qi][1], acc[qi][2], acc[qi][3]);
    }
    __syncthreads();

#pragma unroll
    for (int i = 0; i < 8; i++) {
        int idx = tid + i * 256;  // 0..2047
        int qq  = idx >> 8;
        int d   = idx & 255;
        float r = (sR[0][idx] + sR[1][idx]) + (sR[2][idx] + sR[3][idx]);
        out[((size_t)b * Qn + q0 + qq) * DVn + d] = r;
    }
}

// ---------------------------------------------------------------------------
extern "C" void kernel_launch(void* const* d_in, const int* in_sizes, int n_in,
                              void* d_out, int out_size) {
    const float* queries = (const float*)d_in[0];
    const float* keys    = (const float*)d_in[1];
    const float* values  = (const float*)d_in[2];
    const int*   vlens   = (const int*)d_in[3];
    const float* Wq      = (const float*)d_in[4];
    const float* Wk      = (const float*)d_in[5];
    const float* wv      = (const float*)d_in[6];
    float* out           = (float*)d_out;

    proj_kernel<false><<<dim3(Qn / 64, Bn), 256>>>(queries, Wq, Qn);
    proj_kernel<true><<<dim3(Kn / 64, Bn), 256>>>(keys, Wk, Kn);
    scores_kernel<<<dim3(Kn / 32, 2, Bn), 256>>>(wv);
    softmax_kernel<<<dim3(Qn, Bn), 256>>>(vlens);
    av_kernel<<<dim3(Qn / 8, Bn), 256>>>(values, vlens, out);
}

// round 4
// speedup vs baseline: 1.1709x; 1.1709x over previous
#include <cuda_runtime.h>
#include <cuda_bf16.h>
#include <cstdint>

#define Bn  16
#define Qn  64
#define Kn  1024
#define Dn  256
#define Hn  128
#define DVn 256

// Scratch (device globals; no allocation allowed in kernel_launch)
__device__ float g_kproj[Bn * Kn * Hn];   // 8 MB
__device__ float g_qproj[Bn * Qn * Hn];   // 0.5 MB
__device__ float g_scores[Bn * Qn * Kn];  // 4 MB (scores, then attn in-place)

__device__ __forceinline__ float fast_tanh(float x) {
    float y;
    asm("tanh.approx.f32 %0, %1;" : "=f"(y) : "f"(x));
    return y;
}

// ---------------------------------------------------------------------------
// mma.sync m16n8k16 bf16 (row.col) with fp32 accumulate. compute_80+ PTX,
// so it passes the harness's compute_100 virtual target (tcgen05 does not).
// ---------------------------------------------------------------------------
__device__ __forceinline__ void mma16816(float* d, const uint32_t* a,
                                         const uint32_t* b) {
    asm volatile(
        "mma.sync.aligned.m16n8k16.row.col.f32.bf16.bf16.f32 "
        "{%0,%1,%2,%3}, {%4,%5,%6,%7}, {%8,%9}, {%0,%1,%2,%3};"
        : "+f"(d[0]), "+f"(d[1]), "+f"(d[2]), "+f"(d[3])
        : "r"(a[0]), "r"(a[1]), "r"(a[2]), "r"(a[3]), "r"(b[0]), "r"(b[1]));
}

// ---------------------------------------------------------------------------
// Projection P[r, h] = sum_d X[r, d] * W[d, h] via HMMA with split-bf16
// (x = hi + lo; X*W ~= Xh*Wh + Xl*Wh + Xh*Wl, per-term err ~eps^2).
// Grid = 136 CTAs: cid<128 -> keys/Wk/g_kproj (16384 rows), else queries.
// CTA tile 128 rows x 128 cols; 8 warps as 2(M) x 4(N); warp tile 64x32.
// K staged in chunks of 32 in smem (A hi/lo + B^T hi/lo, 40 KB static).
// ---------------------------------------------------------------------------
#define KC 32
#define APAD 40  // row pad (bf16 units): fragment loads are bank-conflict-free

__global__ void __launch_bounds__(256, 1) proj_mma_kernel(
    const float* __restrict__ keys, const float* __restrict__ queries,
    const float* __restrict__ Wk, const float* __restrict__ Wq) {
    __shared__ __align__(16) __nv_bfloat16 sAhi[128][APAD];
    __shared__ __align__(16) __nv_bfloat16 sAlo[128][APAD];
    __shared__ __align__(16) __nv_bfloat16 sBhi[128][APAD];  // [n][k]
    __shared__ __align__(16) __nv_bfloat16 sBlo[128][APAD];

    const int tid  = threadIdx.x;
    const int wid  = tid >> 5;
    const int lane = tid & 31;
    const int cid  = blockIdx.x;

    const float* X;
    const float* W;
    float* P;
    int row0;
    if (cid < 128) {
        X = keys; W = Wk; P = g_kproj; row0 = cid * 128;
    } else {
        X = queries; W = Wq; P = g_qproj; row0 = (cid - 128) * 128;
    }

    const int wm  = (wid & 1) * 64;   // warp M offset
    const int wn  = (wid >> 1) * 32;  // warp N offset
    const int gid = lane >> 2;        // group id (row within atom)
    const int tig = lane & 3;         // thread in group (k/col pairs)

    float acc[4][4][4];
#pragma unroll
    for (int im = 0; im < 4; im++)
#pragma unroll
        for (int in2 = 0; in2 < 4; in2++)
#pragma unroll
            for (int r = 0; r < 4; r++) acc[im][in2][r] = 0.f;

    for (int kc = 0; kc < Dn; kc += KC) {
        // ---- stage A chunk: 128 rows x 32 k, fp32 -> bf16 hi/lo ----
#pragma unroll
        for (int i = 0; i < 4; i++) {
            int idx = tid + i * 256;          // 1024 float4
            int r = idx >> 3, kq = idx & 7;   // 8 float4 per row
            float4 v = *(const float4*)&X[(size_t)(row0 + r) * Dn + kc + kq * 4];
            __nv_bfloat16 h0 = __float2bfloat16(v.x), h1 = __float2bfloat16(v.y);
            __nv_bfloat16 h2 = __float2bfloat16(v.z), h3 = __float2bfloat16(v.w);
            __nv_bfloat162* ph = (__nv_bfloat162*)&sAhi[r][kq * 4];
            ph[0] = __halves2bfloat162(h0, h1);
            ph[1] = __halves2bfloat162(h2, h3);
            __nv_bfloat162* pl = (__nv_bfloat162*)&sAlo[r][kq * 4];
            pl[0] = __halves2bfloat162(
                __float2bfloat16(v.x - __bfloat162float(h0)),
                __float2bfloat16(v.y - __bfloat162float(h1)));
            pl[1] = __halves2bfloat162(
                __float2bfloat16(v.z - __bfloat162float(h2)),
                __float2bfloat16(v.w - __bfloat162float(h3)));
        }
        // ---- stage B chunk transposed: sB[n][k] = W[kc+k][n] ----
#pragma unroll
        for (int i = 0; i < 4; i++) {
            int idx = tid + i * 256;
            int k = idx >> 5, n4 = idx & 31;  // 32 float4 per k-row
            float4 w = *(const float4*)&W[(size_t)(kc + k) * Hn + n4 * 4];
            float wf[4] = {w.x, w.y, w.z, w.w};
#pragma unroll
            for (int j = 0; j < 4; j++) {
                __nv_bfloat16 h = __float2bfloat16(wf[j]);
                sBhi[n4 * 4 + j][k] = h;
                sBlo[n4 * 4 + j][k] =
                    __float2bfloat16(wf[j] - __bfloat162float(h));
            }
        }
        __syncthreads();

        // ---- 2 k16 steps x 16 atoms x 3 products ----
#pragma unroll
        for (int s = 0; s < 2; s++) {
            const int kb = s * 16 + tig * 2;

            uint32_t Ah[4][4], Al[4][4];
#pragma unroll
            for (int im = 0; im < 4; im++) {
                int r = wm + im * 16 + gid;
                Ah[im][0] = *(const uint32_t*)&sAhi[r][kb];
                Ah[im][1] = *(const uint32_t*)&sAhi[r + 8][kb];
                Ah[im][2] = *(const uint32_t*)&sAhi[r][kb + 8];
                Ah[im][3] = *(const uint32_t*)&sAhi[r + 8][kb + 8];
                Al[im][0] = *(const uint32_t*)&sAlo[r][kb];
                Al[im][1] = *(const uint32_t*)&sAlo[r + 8][kb];
                Al[im][2] = *(const uint32_t*)&sAlo[r][kb + 8];
                Al[im][3] = *(const uint32_t*)&sAlo[r + 8][kb + 8];
            }
            uint32_t Bh[4][2], Bl[4][2];
#pragma unroll
            for (int in2 = 0; in2 < 4; in2++) {
                int n = wn + in2 * 8 + gid;
                Bh[in2][0] = *(const uint32_t*)&sBhi[n][kb];
                Bh[in2][1] = *(const uint32_t*)&sBhi[n][kb + 8];
                Bl[in2][0] = *(const uint32_t*)&sBlo[n][kb];
                Bl[in2][1] = *(const uint32_t*)&sBlo[n][kb + 8];
            }
#pragma unroll
            for (int im = 0; im < 4; im++) {
#pragma unroll
                for (int in2 = 0; in2 < 4; in2++) {
                    mma16816(acc[im][in2], Ah[im], Bh[in2]);
                    mma16816(acc[im][in2], Al[im], Bh[in2]);
                    mma16816(acc[im][in2], Ah[im], Bl[in2]);
                }
            }
        }
        __syncthreads();
    }

    // ---- epilogue: D frag -> global ----
#pragma unroll
    for (int im = 0; im < 4; im++) {
        int r_lo = row0 + wm + im * 16 + gid;
#pragma unroll
        for (int in2 = 0; in2 < 4; in2++) {
            int c = wn + in2 * 8 + tig * 2;
            *(float2*)&P[(size_t)r_lo * Hn + c] =
                make_float2(acc[im][in2][0], acc[im][in2][1]);
            *(float2*)&P[(size_t)(r_lo + 8) * Hn + c] =
                make_float2(acc[im][in2][2], acc[im][in2][3]);
        }
    }
}

// ---------------------------------------------------------------------------
// scores[b, q, k] = sum_h wv[h] * tanh(qproj[b,q,h] + kproj[b,k,h])
// CTA = (k-tile 32, q-half 32, b). smem 33.4 KB (static limit OK).
// ---------------------------------------------------------------------------
__global__ void scores_kernel(const float* __restrict__ wv) {
    const int b   = blockIdx.z;
    const int qh  = blockIdx.y * 32;
    const int k0  = blockIdx.x * 32;
    const int tid = threadIdx.x;

    __shared__ __align__(16) float sQ[32][Hn];   // 16 KB
    __shared__ __align__(16) float sK[32][132];  // 16.9 KB padded rows
    __shared__ __align__(16) float sWv[Hn];

    {
        const float4* src =
            (const float4*)(g_qproj + ((size_t)b * Qn + qh) * Hn);
        float4* dst = (float4*)&sQ[0][0];
#pragma unroll
        for (int i = 0; i < 4; i++) {
            int j = tid + i * 256;
            dst[j] = src[j];
        }
    }
    {
        const float4* src =
            (const float4*)(g_kproj + ((size_t)b * Kn + k0) * Hn);
#pragma unroll
        for (int i = 0; i < 4; i++) {
            int j   = tid + i * 256;
            int row = j >> 5;
            int c4  = j & 31;
            *(float4*)&sK[row][c4 * 4] = src[j];
        }
    }
    if (tid < Hn) sWv[tid] = wv[tid];
    __syncthreads();

    const int kk = tid & 31;
    const int q0 = (tid >> 5) * 4;
    float sc[4];
    sc[0] = sc[1] = sc[2] = sc[3] = 0.f;

#pragma unroll 4
    for (int h = 0; h < Hn; h += 4) {
        float4 kv = *(const float4*)&sK[kk][h];
        float4 w4 = *(const float4*)&sWv[h];
#pragma unroll
        for (int qi = 0; qi < 4; qi++) {
            float4 qv = *(const float4*)&sQ[q0 + qi][h];
            sc[qi] += w4.x * fast_tanh(qv.x + kv.x);
            sc[qi] += w4.y * fast_tanh(qv.y + kv.y);
            sc[qi] += w4.z * fast_tanh(qv.z + kv.z);
            sc[qi] += w4.w * fast_tanh(qv.w + kv.w);
        }
    }

    float* srow = g_scores + ((size_t)b * Qn + qh) * Kn + k0 + kk;
#pragma unroll
    for (int qi = 0; qi < 4; qi++) {
        srow[(size_t)(q0 + qi) * Kn] = sc[qi];
    }
}

// ---------------------------------------------------------------------------
// Masked softmax over K=1024, in place in g_scores.
// ---------------------------------------------------------------------------
__global__ void softmax_kernel(const int* __restrict__ vlen) {
    const int b   = blockIdx.y;
    const int q   = blockIdx.x;
    const int tid = threadIdx.x;

    float* row   = g_scores + ((size_t)b * Qn + q) * Kn;
    const int vl = vlen[b];

    float4 s      = ((const float4*)row)[tid];
    const int kb  = tid * 4;
    if (kb + 0 >= vl) s.x = -1e6f;
    if (kb + 1 >= vl) s.y = -1e6f;
    if (kb + 2 >= vl) s.z = -1e6f;
    if (kb + 3 >= vl) s.w = -1e6f;

    __shared__ float redm[8];
    __shared__ float reds[8];

    float m = fmaxf(fmaxf(s.x, s.y), fmaxf(s.z, s.w));
#pragma unroll
    for (int o = 16; o; o >>= 1) m = fmaxf(m, __shfl_xor_sync(0xffffffffu, m, o));
    if ((tid & 31) == 0) redm[tid >> 5] = m;
    __syncthreads();
    float M = redm[0];
#pragma unroll
    for (int i = 1; i < 8; i++) M = fmaxf(M, redm[i]);

    float e0 = __expf(s.x - M);
    float e1 = __expf(s.y - M);
    float e2 = __expf(s.z - M);
    float e3 = __expf(s.w - M);

    float t = (e0 + e1) + (e2 + e3);
#pragma unroll
    for (int o = 16; o; o >>= 1) t += __shfl_xor_sync(0xffffffffu, t, o);
    if ((tid & 31) == 0) reds[tid >> 5] = t;
    __syncthreads();
    float S = reds[0];
#pragma unroll
    for (int i = 1; i < 8; i++) S += reds[i];

    float inv = 1.0f / S;
    ((float4*)row)[tid] = make_float4(e0 * inv, e1 * inv, e2 * inv, e3 * inv);
}

// ---------------------------------------------------------------------------
// out[b, q, d] = sum_k attn[b,q,k] * values[b,k,d], k loop cut at vlen.
// ---------------------------------------------------------------------------
__global__ void av_kernel(const float* __restrict__ V,
                          const int* __restrict__ vlen,
                          float* __restrict__ out) {
    const int b   = blockIdx.y;
    const int q0  = blockIdx.x * 8;
    const int tid = threadIdx.x;
    const int ks  = tid >> 6;
    const int c   = tid & 63;
    const int vl  = vlen[b];

    __shared__ __align__(16) float sA[8][128];
    __shared__ __align__(16) float sR[4][2048];

    float acc[8][4];
#pragma unroll
    for (int i = 0; i < 8; i++) {
        acc[i][0] = acc[i][1] = acc[i][2] = acc[i][3] = 0.f;
    }

    const float* Vb = V + (size_t)b * Kn * DVn;
    const float* Ab = g_scores + ((size_t)b * Qn + q0) * Kn;

    for (int k0 = 0; k0 < vl; k0 += 128) {
#pragma unroll
        for (int i = 0; i < 4; i++) {
            int j  = tid + i * 256;
            int qq = j >> 7, kk = j & 127;
            sA[qq][kk] = Ab[(size_t)qq * Kn + k0 + kk];
        }
        __syncthreads();

#pragma unroll 8
        for (int jj = 0; jj < 32; jj++) {
            int k    = ks + jj * 4;
            float4 v = *(const float4*)&Vb[(size_t)(k0 + k) * DVn + c * 4];
#pragma unroll
            for (int qi = 0; qi < 8; qi++) {
                float a = sA[qi][k];
                acc[qi][0] += a * v.x;
                acc[qi][1] += a * v.y;
                acc[qi][2] += a * v.z;
                acc[qi][3] += a * v.w;
            }
        }
        __syncthreads();
    }

#pragma unroll
    for (int qi = 0; qi < 8; qi++) {
        *(float4*)&sR[ks][qi * 256 + c * 4] =
            make_float4(acc[qi][0], acc[qi][1], acc[qi][2], acc[qi][3]);
    }
    __syncthreads();

#pragma unroll
    for (int i = 0; i < 8; i++) {
        int idx = tid + i * 256;
        int qq  = idx >> 8;
        int d   = idx & 255;
        float r = (sR[0][idx] + sR[1][idx]) + (sR[2][idx] + sR[3][idx]);
        out[((size_t)b * Qn + q0 + qq) * DVn + d] = r;
    }
}

// ---------------------------------------------------------------------------
extern "C" void kernel_launch(void* const* d_in, const int* in_sizes, int n_in,
                              void* d_out, int out_size) {
    const float* queries = (const float*)d_in[0];
    const float* keys    = (const float*)d_in[1];
    const float* values  = (const float*)d_in[2];
    const int*   vlens   = (const int*)d_in[3];
    const float* Wq      = (const float*)d_in[4];
    const float* Wk      = (const float*)d_in[5];
    const float* wv      = (const float*)d_in[6];
    float* out           = (float*)d_out;

    proj_mma_kernel<<<136, 256>>>(keys, queries, Wk, Wq);
    scores_kernel<<<dim3(Kn / 32, 2, Bn), 256>>>(wv);
    softmax_kernel<<<dim3(Qn, Bn), 256>>>(vlens);
    av_kernel<<<dim3(Qn / 8, Bn), 256>>>(values, vlens, out);
}

// round 6
// speedup vs baseline: 1.3821x; 1.1805x over previous
#include <cuda_runtime.h>
#include <cuda_bf16.h>
#include <cstdint>

#define Bn  16
#define Qn  64
#define Kn  1024
#define Dn  256
#define Hn  128
#define DVn 256

// Scratch (device globals; no allocation allowed in kernel_launch)
__device__ float g_kproj[Bn * Kn * Hn];   // 8 MB
__device__ float g_qproj[Bn * Qn * Hn];   // 0.5 MB
__device__ float g_scores[Bn * Qn * Kn];  // 4 MB (scores, then attn in-place)

__device__ __forceinline__ float fast_tanh(float x) {
    float y;
    asm("tanh.approx.f32 %0, %1;" : "=f"(y) : "f"(x));
    return y;
}

// ---------------------------------------------------------------------------
// mma.sync m16n8k16 bf16 (row.col) with fp32 accumulate. compute_80+ PTX,
// so it passes the harness's compute_100 virtual target (tcgen05 does not).
// ---------------------------------------------------------------------------
__device__ __forceinline__ void mma16816(float* d, const uint32_t* a,
                                         const uint32_t* b) {
    asm volatile(
        "mma.sync.aligned.m16n8k16.row.col.f32.bf16.bf16.f32 "
        "{%0,%1,%2,%3}, {%4,%5,%6,%7}, {%8,%9}, {%0,%1,%2,%3};"
        : "+f"(d[0]), "+f"(d[1]), "+f"(d[2]), "+f"(d[3])
        : "r"(a[0]), "r"(a[1]), "r"(a[2]), "r"(a[3]), "r"(b[0]), "r"(b[1]));
}

// ---------------------------------------------------------------------------
// Projection P[r, h] = sum_d X[r, d] * W[d, h] via HMMA with split-bf16
// (x = hi + lo; X*W ~= Xh*Wh + Xl*Wh + Xh*Wl, per-term err ~eps^2).
// Grid = 136 CTAs: cid<128 -> keys/Wk/g_kproj (16384 rows), else queries.
// CTA tile 128 rows x 128 cols; 8 warps as 2(M) x 4(N); warp tile 64x32.
// K staged in chunks of 32 in smem (A hi/lo + B^T hi/lo, 40 KB static).
// ---------------------------------------------------------------------------
#define KC 32
#define APAD 40  // row pad (bf16 units): fragment loads are bank-conflict-free

__global__ void __launch_bounds__(256, 1) proj_mma_kernel(
    const float* __restrict__ keys, const float* __restrict__ queries,
    const float* __restrict__ Wk, const float* __restrict__ Wq) {
    __shared__ __align__(16) __nv_bfloat16 sAhi[128][APAD];
    __shared__ __align__(16) __nv_bfloat16 sAlo[128][APAD];
    __shared__ __align__(16) __nv_bfloat16 sBhi[128][APAD];  // [n][k]
    __shared__ __align__(16) __nv_bfloat16 sBlo[128][APAD];

    const int tid  = threadIdx.x;
    const int wid  = tid >> 5;
    const int lane = tid & 31;
    const int cid  = blockIdx.x;

    const float* X;
    const float* W;
    float* P;
    int row0;
    if (cid < 128) {
        X = keys; W = Wk; P = g_kproj; row0 = cid * 128;
    } else {
        X = queries; W = Wq; P = g_qproj; row0 = (cid - 128) * 128;
    }

    const int wm  = (wid & 1) * 64;   // warp M offset
    const int wn  = (wid >> 1) * 32;  // warp N offset
    const int gid = lane >> 2;        // group id (row within atom)
    const int tig = lane & 3;         // thread in group (k/col pairs)

    float acc[4][4][4];
#pragma unroll
    for (int im = 0; im < 4; im++)
#pragma unroll
        for (int in2 = 0; in2 < 4; in2++)
#pragma unroll
            for (int r = 0; r < 4; r++) acc[im][in2][r] = 0.f;

    for (int kc = 0; kc < Dn; kc += KC) {
        // ---- stage A chunk: 128 rows x 32 k, fp32 -> bf16 hi/lo ----
#pragma unroll
        for (int i = 0; i < 4; i++) {
            int idx = tid + i * 256;          // 1024 float4
            int r = idx >> 3, kq = idx & 7;   // 8 float4 per row
            float4 v = *(const float4*)&X[(size_t)(row0 + r) * Dn + kc + kq * 4];
            __nv_bfloat16 h0 = __float2bfloat16(v.x), h1 = __float2bfloat16(v.y);
            __nv_bfloat16 h2 = __float2bfloat16(v.z), h3 = __float2bfloat16(v.w);
            __nv_bfloat162* ph = (__nv_bfloat162*)&sAhi[r][kq * 4];
            ph[0] = __halves2bfloat162(h0, h1);
            ph[1] = __halves2bfloat162(h2, h3);
            __nv_bfloat162* pl = (__nv_bfloat162*)&sAlo[r][kq * 4];
            pl[0] = __halves2bfloat162(
                __float2bfloat16(v.x - __bfloat162float(h0)),
                __float2bfloat16(v.y - __bfloat162float(h1)));
            pl[1] = __halves2bfloat162(
                __float2bfloat16(v.z - __bfloat162float(h2)),
                __float2bfloat16(v.w - __bfloat162float(h3)));
        }
        // ---- stage B chunk transposed: sB[n][k] = W[kc+k][n] ----
#pragma unroll
        for (int i = 0; i < 4; i++) {
            int idx = tid + i * 256;
            int k = idx >> 5, n4 = idx & 31;  // 32 float4 per k-row
            float4 w = *(const float4*)&W[(size_t)(kc + k) * Hn + n4 * 4];
            float wf[4] = {w.x, w.y, w.z, w.w};
#pragma unroll
            for (int j = 0; j < 4; j++) {
                __nv_bfloat16 h = __float2bfloat16(wf[j]);
                sBhi[n4 * 4 + j][k] = h;
                sBlo[n4 * 4 + j][k] =
                    __float2bfloat16(wf[j] - __bfloat162float(h));
            }
        }
        __syncthreads();

        // ---- 2 k16 steps x 16 atoms x 3 products ----
#pragma unroll
        for (int s = 0; s < 2; s++) {
            const int kb = s * 16 + tig * 2;

            uint32_t Ah[4][4], Al[4][4];
#pragma unroll
            for (int im = 0; im < 4; im++) {
                int r = wm + im * 16 + gid;
                Ah[im][0] = *(const uint32_t*)&sAhi[r][kb];
                Ah[im][1] = *(const uint32_t*)&sAhi[r + 8][kb];
                Ah[im][2] = *(const uint32_t*)&sAhi[r][kb + 8];
                Ah[im][3] = *(const uint32_t*)&sAhi[r + 8][kb + 8];
                Al[im][0] = *(const uint32_t*)&sAlo[r][kb];
                Al[im][1] = *(const uint32_t*)&sAlo[r + 8][kb];
                Al[im][2] = *(const uint32_t*)&sAlo[r][kb + 8];
                Al[im][3] = *(const uint32_t*)&sAlo[r + 8][kb + 8];
            }
            uint32_t Bh[4][2], Bl[4][2];
#pragma unroll
            for (int in2 = 0; in2 < 4; in2++) {
                int n = wn + in2 * 8 + gid;
                Bh[in2][0] = *(const uint32_t*)&sBhi[n][kb];
                Bh[in2][1] = *(const uint32_t*)&sBhi[n][kb + 8];
                Bl[in2][0] = *(const uint32_t*)&sBlo[n][kb];
                Bl[in2][1] = *(const uint32_t*)&sBlo[n][kb + 8];
            }
#pragma unroll
            for (int im = 0; im < 4; im++) {
#pragma unroll
                for (int in2 = 0; in2 < 4; in2++) {
                    mma16816(acc[im][in2], Ah[im], Bh[in2]);
                    mma16816(acc[im][in2], Al[im], Bh[in2]);
                    mma16816(acc[im][in2], Ah[im], Bl[in2]);
                }
            }
        }
        __syncthreads();
    }

    // ---- epilogue: D frag -> global ----
#pragma unroll
    for (int im = 0; im < 4; im++) {
        int r_lo = row0 + wm + im * 16 + gid;
#pragma unroll
        for (int in2 = 0; in2 < 4; in2++) {
            int c = wn + in2 * 8 + tig * 2;
            *(float2*)&P[(size_t)r_lo * Hn + c] =
                make_float2(acc[im][in2][0], acc[im][in2][1]);
            *(float2*)&P[(size_t)(r_lo + 8) * Hn + c] =
                make_float2(acc[im][in2][2], acc[im][in2][3]);
        }
    }
}

// ---------------------------------------------------------------------------
// scores[b, q, k] = sum_h wv[h] * tanh(qproj[b,q,h] + kproj[b,k,h])
// CTA = (k-tile 32, q-half 32, b). smem 33.4 KB (static limit OK).
// ---------------------------------------------------------------------------
__global__ void scores_kernel(const float* __restrict__ wv) {
    const int b   = blockIdx.z;
    const int qh  = blockIdx.y * 32;
    const int k0  = blockIdx.x * 32;
    const int tid = threadIdx.x;

    __shared__ __align__(16) float sQ[32][Hn];   // 16 KB
    __shared__ __align__(16) float sK[32][132];  // 16.9 KB padded rows
    __shared__ __align__(16) float sWv[Hn];

    {
        const float4* src =
            (const float4*)(g_qproj + ((size_t)b * Qn + qh) * Hn);
        float4* dst = (float4*)&sQ[0][0];
#pragma unroll
        for (int i = 0; i < 4; i++) {
            int j = tid + i * 256;
            dst[j] = src[j];
        }
    }
    {
        const float4* src =
            (const float4*)(g_kproj + ((size_t)b * Kn + k0) * Hn);
#pragma unroll
        for (int i = 0; i < 4; i++) {
            int j   = tid + i * 256;
            int row = j >> 5;
            int c4  = j & 31;
            *(float4*)&sK[row][c4 * 4] = src[j];
        }
    }
    if (tid < Hn) sWv[tid] = wv[tid];
    __syncthreads();

    const int kk = tid & 31;
    const int q0 = (tid >> 5) * 4;
    float sc[4];
    sc[0] = sc[1] = sc[2] = sc[3] = 0.f;

#pragma unroll 4
    for (int h = 0; h < Hn; h += 4) {
        float4 kv = *(const float4*)&sK[kk][h];
        float4 w4 = *(const float4*)&sWv[h];
#pragma unroll
        for (int qi = 0; qi < 4; qi++) {
            float4 qv = *(const float4*)&sQ[q0 + qi][h];
            sc[qi] += w4.x * fast_tanh(qv.x + kv.x);
            sc[qi] += w4.y * fast_tanh(qv.y + kv.y);
            sc[qi] += w4.z * fast_tanh(qv.z + kv.z);
            sc[qi] += w4.w * fast_tanh(qv.w + kv.w);
        }
    }

    float* srow = g_scores + ((size_t)b * Qn + qh) * Kn + k0 + kk;
#pragma unroll
    for (int qi = 0; qi < 4; qi++) {
        srow[(size_t)(q0 + qi) * Kn] = sc[qi];
    }
}

// ---------------------------------------------------------------------------
// Masked softmax over K=1024, in place in g_scores.
// ---------------------------------------------------------------------------
__global__ void softmax_kernel(const int* __restrict__ vlen) {
    const int b   = blockIdx.y;
    const int q   = blockIdx.x;
    const int tid = threadIdx.x;

    float* row   = g_scores + ((size_t)b * Qn + q) * Kn;
    const int vl = vlen[b];

    float4 s      = ((const float4*)row)[tid];
    const int kb  = tid * 4;
    if (kb + 0 >= vl) s.x = -1e6f;
    if (kb + 1 >= vl) s.y = -1e6f;
    if (kb + 2 >= vl) s.z = -1e6f;
    if (kb + 3 >= vl) s.w = -1e6f;

    __shared__ float redm[8];
    __shared__ float reds[8];

    float m = fmaxf(fmaxf(s.x, s.y), fmaxf(s.z, s.w));
#pragma unroll
    for (int o = 16; o; o >>= 1) m = fmaxf(m, __shfl_xor_sync(0xffffffffu, m, o));
    if ((tid & 31) == 0) redm[tid >> 5] = m;
    __syncthreads();
    float M = redm[0];
#pragma unroll
    for (int i = 1; i < 8; i++) M = fmaxf(M, redm[i]);

    float e0 = __expf(s.x - M);
    float e1 = __expf(s.y - M);
    float e2 = __expf(s.z - M);
    float e3 = __expf(s.w - M);

    float t = (e0 + e1) + (e2 + e3);
#pragma unroll
    for (int o = 16; o; o >>= 1) t += __shfl_xor_sync(0xffffffffu, t, o);
    if ((tid & 31) == 0) reds[tid >> 5] = t;
    __syncthreads();
    float S = reds[0];
#pragma unroll
    for (int i = 1; i < 8; i++) S += reds[i];

    float inv = 1.0f / S;
    ((float4*)row)[tid] = make_float4(e0 * inv, e1 * inv, e2 * inv, e3 * inv);
}

// ---------------------------------------------------------------------------
// out[b, q, d] = sum_k attn[b,q,k] * values[b,k,d], k loop cut at vlen.
// CTA = (q, b) -> 1024 CTAs, thread owns one d column. attn row staged in
// smem (one float4 per thread = exactly 1024 floats; R5 bug was 4x that,
// overflowing smem). V loads coalesced, 8 independent accumulator chains.
// ---------------------------------------------------------------------------
__global__ void __launch_bounds__(256) av_kernel(
    const float* __restrict__ V, const int* __restrict__ vlen,
    float* __restrict__ out) {
    const int b   = blockIdx.y;
    const int q   = blockIdx.x;
    const int tid = threadIdx.x;
    const int vl  = vlen[b];

    __shared__ __align__(16) float sA[Kn];

    const float* Arow = g_scores + ((size_t)b * Qn + q) * Kn;
    ((float4*)sA)[tid] = ((const float4*)Arow)[tid];  // 256 x 16B = 4 KB row
    __syncthreads();

    const float* Vc = V + (size_t)b * Kn * DVn + tid;

    float a0 = 0.f, a1 = 0.f, a2 = 0.f, a3 = 0.f;
    float a4 = 0.f, a5 = 0.f, a6 = 0.f, a7 = 0.f;

    int k = 0;
    for (; k + 8 <= vl; k += 8) {
        a0 += sA[k + 0] * Vc[(size_t)(k + 0) * DVn];
        a1 += sA[k + 1] * Vc[(size_t)(k + 1) * DVn];
        a2 += sA[k + 2] * Vc[(size_t)(k + 2) * DVn];
        a3 += sA[k + 3] * Vc[(size_t)(k + 3) * DVn];
        a4 += sA[k + 4] * Vc[(size_t)(k + 4) * DVn];
        a5 += sA[k + 5] * Vc[(size_t)(k + 5) * DVn];
        a6 += sA[k + 6] * Vc[(size_t)(k + 6) * DVn];
        a7 += sA[k + 7] * Vc[(size_t)(k + 7) * DVn];
    }
    for (; k < vl; k++) {
        a0 += sA[k] * Vc[(size_t)k * DVn];
    }

    out[((size_t)b * Qn + q) * DVn + tid] =
        ((a0 + a1) + (a2 + a3)) + ((a4 + a5) + (a6 + a7));
}

// ---------------------------------------------------------------------------
extern "C" void kernel_launch(void* const* d_in, const int* in_sizes, int n_in,
                              void* d_out, int out_size) {
    const float* queries = (const float*)d_in[0];
    const float* keys    = (const float*)d_in[1];
    const float* values  = (const float*)d_in[2];
    const int*   vlens   = (const int*)d_in[3];
    const float* Wq      = (const float*)d_in[4];
    const float* Wk      = (const float*)d_in[5];
    const float* wv      = (const float*)d_in[6];
    float* out           = (float*)d_out;

    proj_mma_kernel<<<136, 256>>>(keys, queries, Wk, Wq);
    scores_kernel<<<dim3(Kn / 32, 2, Bn), 256>>>(wv);
    softmax_kernel<<<dim3(Qn, Bn), 256>>>(vlens);
    av_kernel<<<dim3(Qn, Bn), 256>>>(values, vlens, out);
}

// round 7
// speedup vs baseline: 1.5032x; 1.0876x over previous
#include <cuda_runtime.h>
#include <cuda_bf16.h>
#include <cstdint>

#define Bn  16
#define Qn  64
#define Kn  1024
#define Dn  256
#define Hn  128
#define DVn 256

// Scratch (device globals; no allocation allowed in kernel_launch)
__device__ float g_kproj[Bn * Kn * Hn];        // 8 MB
__device__ float g_qproj[Bn * Qn * Hn];        // 0.5 MB
__device__ float g_scores[Bn * Qn * Kn];       // 4 MB (scores, then attn)
__device__ float g_part[8][Bn][Qn][DVn];       // 8 MB AV partials (zero-init;
                                               // chunks beyond vlen are never
                                               // written and stay exactly 0)

__device__ __forceinline__ float fast_tanh(float x) {
    float y;
    asm("tanh.approx.f32 %0, %1;" : "=f"(y) : "f"(x));
    return y;
}

// ---------------------------------------------------------------------------
// mma.sync m16n8k16 bf16 (row.col) with fp32 accumulate. compute_80+ PTX,
// so it passes the harness's compute_100 virtual target (tcgen05 does not).
// ---------------------------------------------------------------------------
__device__ __forceinline__ void mma16816(float* d, const uint32_t* a,
                                         const uint32_t* b) {
    asm volatile(
        "mma.sync.aligned.m16n8k16.row.col.f32.bf16.bf16.f32 "
        "{%0,%1,%2,%3}, {%4,%5,%6,%7}, {%8,%9}, {%0,%1,%2,%3};"
        : "+f"(d[0]), "+f"(d[1]), "+f"(d[2]), "+f"(d[3])
        : "r"(a[0]), "r"(a[1]), "r"(a[2]), "r"(a[3]), "r"(b[0]), "r"(b[1]));
}

__device__ __forceinline__ __nv_bfloat162 hi2(float a, float b) {
    return __halves2bfloat162(__float2bfloat16(a), __float2bfloat16(b));
}
__device__ __forceinline__ __nv_bfloat162 lo2(float a, float b) {
    return __halves2bfloat162(
        __float2bfloat16(a - __bfloat162float(__float2bfloat16(a))),
        __float2bfloat16(b - __bfloat162float(__float2bfloat16(b))));
}

// ---------------------------------------------------------------------------
// Projection P[r, h] = sum_d X[r, d] * W[d, h] via HMMA with split-bf16
// (x = hi + lo; X*W ~= Xh*Wh + Xl*Wh + Xh*Wl, per-term err ~eps^2).
// Grid = 136 CTAs: cid<128 -> keys/Wk/g_kproj (16384 rows), else queries.
// CTA tile 128 rows x 128 cols; 8 warps as 2(M) x 4(N); warp tile 64x32.
// ---------------------------------------------------------------------------
#define KC 32
#define APAD 40  // row pad (bf16 units): fragment loads are bank-conflict-free

__global__ void __launch_bounds__(256, 1) proj_mma_kernel(
    const float* __restrict__ keys, const float* __restrict__ queries,
    const float* __restrict__ Wk, const float* __restrict__ Wq) {
    __shared__ __align__(16) __nv_bfloat16 sAhi[128][APAD];
    __shared__ __align__(16) __nv_bfloat16 sAlo[128][APAD];
    __shared__ __align__(16) __nv_bfloat16 sBhi[128][APAD];  // [n][k]
    __shared__ __align__(16) __nv_bfloat16 sBlo[128][APAD];

    const int tid  = threadIdx.x;
    const int wid  = tid >> 5;
    const int lane = tid & 31;
    const int cid  = blockIdx.x;

    const float* X;
    const float* W;
    float* P;
    int row0;
    if (cid < 128) {
        X = keys; W = Wk; P = g_kproj; row0 = cid * 128;
    } else {
        X = queries; W = Wq; P = g_qproj; row0 = (cid - 128) * 128;
    }

    const int wm  = (wid & 1) * 64;
    const int wn  = (wid >> 1) * 32;
    const int gid = lane >> 2;
    const int tig = lane & 3;

    float acc[4][4][4];
#pragma unroll
    for (int im = 0; im < 4; im++)
#pragma unroll
        for (int in2 = 0; in2 < 4; in2++)
#pragma unroll
            for (int r = 0; r < 4; r++) acc[im][in2][r] = 0.f;

    for (int kc = 0; kc < Dn; kc += KC) {
#pragma unroll
        for (int i = 0; i < 4; i++) {
            int idx = tid + i * 256;
            int r = idx >> 3, kq = idx & 7;
            float4 v = *(const float4*)&X[(size_t)(row0 + r) * Dn + kc + kq * 4];
            __nv_bfloat162* ph = (__nv_bfloat162*)&sAhi[r][kq * 4];
            ph[0] = hi2(v.x, v.y);
            ph[1] = hi2(v.z, v.w);
            __nv_bfloat162* pl = (__nv_bfloat162*)&sAlo[r][kq * 4];
            pl[0] = lo2(v.x, v.y);
            pl[1] = lo2(v.z, v.w);
        }
#pragma unroll
        for (int i = 0; i < 4; i++) {
            int idx = tid + i * 256;
            int k = idx >> 5, n4 = idx & 31;
            float4 w = *(const float4*)&W[(size_t)(kc + k) * Hn + n4 * 4];
            float wf[4] = {w.x, w.y, w.z, w.w};
#pragma unroll
            for (int j = 0; j < 4; j++) {
                __nv_bfloat16 h = __float2bfloat16(wf[j]);
                sBhi[n4 * 4 + j][k] = h;
                sBlo[n4 * 4 + j][k] =
                    __float2bfloat16(wf[j] - __bfloat162float(h));
            }
        }
        __syncthreads();

#pragma unroll
        for (int s = 0; s < 2; s++) {
            const int kb = s * 16 + tig * 2;

            uint32_t Ah[4][4], Al[4][4];
#pragma unroll
            for (int im = 0; im < 4; im++) {
                int r = wm + im * 16 + gid;
                Ah[im][0] = *(const uint32_t*)&sAhi[r][kb];
                Ah[im][1] = *(const uint32_t*)&sAhi[r + 8][kb];
                Ah[im][2] = *(const uint32_t*)&sAhi[r][kb + 8];
                Ah[im][3] = *(const uint32_t*)&sAhi[r + 8][kb + 8];
                Al[im][0] = *(const uint32_t*)&sAlo[r][kb];
                Al[im][1] = *(const uint32_t*)&sAlo[r + 8][kb];
                Al[im][2] = *(const uint32_t*)&sAlo[r][kb + 8];
                Al[im][3] = *(const uint32_t*)&sAlo[r + 8][kb + 8];
            }
            uint32_t Bh[4][2], Bl[4][2];
#pragma unroll
            for (int in2 = 0; in2 < 4; in2++) {
                int n = wn + in2 * 8 + gid;
                Bh[in2][0] = *(const uint32_t*)&sBhi[n][kb];
                Bh[in2][1] = *(const uint32_t*)&sBhi[n][kb + 8];
                Bl[in2][0] = *(const uint32_t*)&sBlo[n][kb];
                Bl[in2][1] = *(const uint32_t*)&sBlo[n][kb + 8];
            }
#pragma unroll
            for (int im = 0; im < 4; im++) {
#pragma unroll
                for (int in2 = 0; in2 < 4; in2++) {
                    mma16816(acc[im][in2], Ah[im], Bh[in2]);
                    mma16816(acc[im][in2], Al[im], Bh[in2]);
                    mma16816(acc[im][in2], Ah[im], Bl[in2]);
                }
            }
        }
        __syncthreads();
    }

#pragma unroll
    for (int im = 0; im < 4; im++) {
        int r_lo = row0 + wm + im * 16 + gid;
#pragma unroll
        for (int in2 = 0; in2 < 4; in2++) {
            int c = wn + in2 * 8 + tig * 2;
            *(float2*)&P[(size_t)r_lo * Hn + c] =
                make_float2(acc[im][in2][0], acc[im][in2][1]);
            *(float2*)&P[(size_t)(r_lo + 8) * Hn + c] =
                make_float2(acc[im][in2][2], acc[im][in2][3]);
        }
    }
}

// ---------------------------------------------------------------------------
// scores[b, q, k] = sum_h wv[h] * tanh(qproj[b,q,h] + kproj[b,k,h])
// CTA = (k-tile 32, q-half 32, b). smem 33.4 KB (static limit OK).
// ---------------------------------------------------------------------------
__global__ void scores_kernel(const float* __restrict__ wv) {
    const int b   = blockIdx.z;
    const int qh  = blockIdx.y * 32;
    const int k0  = blockIdx.x * 32;
    const int tid = threadIdx.x;

    __shared__ __align__(16) float sQ[32][Hn];
    __shared__ __align__(16) float sK[32][132];
    __shared__ __align__(16) float sWv[Hn];

    {
        const float4* src =
            (const float4*)(g_qproj + ((size_t)b * Qn + qh) * Hn);
        float4* dst = (float4*)&sQ[0][0];
#pragma unroll
        for (int i = 0; i < 4; i++) {
            int j = tid + i * 256;
            dst[j] = src[j];
        }
    }
    {
        const float4* src =
            (const float4*)(g_kproj + ((size_t)b * Kn + k0) * Hn);
#pragma unroll
        for (int i = 0; i < 4; i++) {
            int j   = tid + i * 256;
            int row = j >> 5;
            int c4  = j & 31;
            *(float4*)&sK[row][c4 * 4] = src[j];
        }
    }
    if (tid < Hn) sWv[tid] = wv[tid];
    __syncthreads();

    const int kk = tid & 31;
    const int q0 = (tid >> 5) * 4;
    float sc[4];
    sc[0] = sc[1] = sc[2] = sc[3] = 0.f;

#pragma unroll 4
    for (int h = 0; h < Hn; h += 4) {
        float4 kv = *(const float4*)&sK[kk][h];
        float4 w4 = *(const float4*)&sWv[h];
#pragma unroll
        for (int qi = 0; qi < 4; qi++) {
            float4 qv = *(const float4*)&sQ[q0 + qi][h];
            sc[qi] += w4.x * fast_tanh(qv.x + kv.x);
            sc[qi] += w4.y * fast_tanh(qv.y + kv.y);
            sc[qi] += w4.z * fast_tanh(qv.z + kv.z);
            sc[qi] += w4.w * fast_tanh(qv.w + kv.w);
        }
    }

    float* srow = g_scores + ((size_t)b * Qn + qh) * Kn + k0 + kk;
#pragma unroll
    for (int qi = 0; qi < 4; qi++) {
        srow[(size_t)(q0 + qi) * Kn] = sc[qi];
    }
}

// ---------------------------------------------------------------------------
// Masked softmax over K=1024, in place in g_scores.
// Invalid lanes (k >= vlen) -> exactly 0 after exp underflow.
// ---------------------------------------------------------------------------
__global__ void softmax_kernel(const int* __restrict__ vlen) {
    const int b   = blockIdx.y;
    const int q   = blockIdx.x;
    const int tid = threadIdx.x;

    float* row   = g_scores + ((size_t)b * Qn + q) * Kn;
    const int vl = vlen[b];

    float4 s      = ((const float4*)row)[tid];
    const int kb  = tid * 4;
    if (kb + 0 >= vl) s.x = -1e6f;
    if (kb + 1 >= vl) s.y = -1e6f;
    if (kb + 2 >= vl) s.z = -1e6f;
    if (kb + 3 >= vl) s.w = -1e6f;

    __shared__ float redm[8];
    __shared__ float reds[8];

    float m = fmaxf(fmaxf(s.x, s.y), fmaxf(s.z, s.w));
#pragma unroll
    for (int o = 16; o; o >>= 1) m = fmaxf(m, __shfl_xor_sync(0xffffffffu, m, o));
    if ((tid & 31) == 0) redm[tid >> 5] = m;
    __syncthreads();
    float M = redm[0];
#pragma unroll
    for (int i = 1; i < 8; i++) M = fmaxf(M, redm[i]);

    float e0 = __expf(s.x - M);
    float e1 = __expf(s.y - M);
    float e2 = __expf(s.z - M);
    float e3 = __expf(s.w - M);

    float t = (e0 + e1) + (e2 + e3);
#pragma unroll
    for (int o = 16; o; o >>= 1) t += __shfl_xor_sync(0xffffffffu, t, o);
    if ((tid & 31) == 0) reds[tid >> 5] = t;
    __syncthreads();
    float S = reds[0];
#pragma unroll
    for (int i = 1; i < 8; i++) S += reds[i];

    float inv = 1.0f / S;
    ((float4*)row)[tid] = make_float4(e0 * inv, e1 * inv, e2 * inv, e3 * inv);
}

// ---------------------------------------------------------------------------
// AV as HMMA GEMM: out_partial[ck][b] = attn[b][:, ck*128:+128] @ V[b][ck...].
// CTA = (k-chunk 128, b) = 128 CTAs; split-bf16 3-product like proj.
// Chunks beyond vlen return early: their g_part slice is never written and
// stays exactly 0 (attn there is exactly 0). Warp tile 32(M) x 64(N).
// ---------------------------------------------------------------------------
#define VPAD 36

__global__ void __launch_bounds__(256, 1) av_mma_kernel(
    const float* __restrict__ V, const int* __restrict__ vlen) {
    const int b  = blockIdx.y;
    const int ck = blockIdx.x;
    const int k0 = ck * 128;
    if (k0 >= vlen[b]) return;  // uniform per CTA

    __shared__ __align__(16) __nv_bfloat16 sAh[64][APAD];   // attn hi
    __shared__ __align__(16) __nv_bfloat16 sAl[64][APAD];   // attn lo
    __shared__ __align__(16) __nv_bfloat16 sVh[256][VPAD];  // V^T hi [n][k]
    __shared__ __align__(16) __nv_bfloat16 sVl[256][VPAD];  // V^T lo

    const int tid  = threadIdx.x;
    const int wid  = tid >> 5;
    const int lane = tid & 31;
    const int gid  = lane >> 2;
    const int tig  = lane & 3;
    const int wm   = (wid & 1) * 32;   // warp M offset (2 x 32 = 64 q)
    const int wn   = (wid >> 1) * 64;  // warp N offset (4 x 64 = 256 dv)

    float acc[2][8][4];
#pragma unroll
    for (int im = 0; im < 2; im++)
#pragma unroll
        for (int j = 0; j < 8; j++)
#pragma unroll
            for (int r = 0; r < 4; r++) acc[im][j][r] = 0.f;

    const float* Ab = g_scores + ((size_t)b * Qn) * Kn + k0;
    const float* Vb = V + ((size_t)b * Kn + k0) * DVn;

    for (int kc = 0; kc < 128; kc += KC) {
        // ---- stage attn chunk: 64 q x 32 k, hi/lo ----
#pragma unroll
        for (int i = 0; i < 2; i++) {
            int idx = tid + i * 256;          // 512 float4
            int r = idx >> 3, kq = idx & 7;   // 8 float4 per q-row
            float4 v = *(const float4*)&Ab[(size_t)r * Kn + kc + kq * 4];
            __nv_bfloat162* ph = (__nv_bfloat162*)&sAh[r][kq * 4];
            ph[0] = hi2(v.x, v.y);
            ph[1] = hi2(v.z, v.w);
            __nv_bfloat162* pl = (__nv_bfloat162*)&sAl[r][kq * 4];
            pl[0] = lo2(v.x, v.y);
            pl[1] = lo2(v.z, v.w);
        }
        // ---- stage V^T chunk: sV[n][k] = V[kc+k][n], 32 k x 256 n ----
#pragma unroll
        for (int i = 0; i < 8; i++) {
            int idx = tid + i * 256;          // 2048 float4
            int k = idx >> 6, n4 = idx & 63;  // 64 float4 per k-row
            float4 w = *(const float4*)&Vb[(size_t)(kc + k) * DVn + n4 * 4];
            float wf[4] = {w.x, w.y, w.z, w.w};
#pragma unroll
            for (int j = 0; j < 4; j++) {
                __nv_bfloat16 h = __float2bfloat16(wf[j]);
                sVh[n4 * 4 + j][k] = h;
                sVl[n4 * 4 + j][k] =
                    __float2bfloat16(wf[j] - __bfloat162float(h));
            }
        }
        __syncthreads();

#pragma unroll
        for (int s = 0; s < 2; s++) {
            const int kb = s * 16 + tig * 2;

            uint32_t Ah2[2][4], Al2[2][4];
#pragma unroll
            for (int im = 0; im < 2; im++) {
                int r = wm + im * 16 + gid;
                Ah2[im][0] = *(const uint32_t*)&sAh[r][kb];
                Ah2[im][1] = *(const uint32_t*)&sAh[r + 8][kb];
                Ah2[im][2] = *(const uint32_t*)&sAh[r][kb + 8];
                Ah2[im][3] = *(const uint32_t*)&sAh[r + 8][kb + 8];
                Al2[im][0] = *(const uint32_t*)&sAl[r][kb];
                Al2[im][1] = *(const uint32_t*)&sAl[r + 8][kb];
                Al2[im][2] = *(const uint32_t*)&sAl[r][kb + 8];
                Al2[im][3] = *(const uint32_t*)&sAl[r + 8][kb + 8];
            }
#pragma unroll
            for (int j = 0; j < 8; j++) {
                int n = wn + j * 8 + gid;
                uint32_t Bh[2], Bl[2];
                Bh[0] = *(const uint32_t*)&sVh[n][kb];
                Bh[1] = *(const uint32_t*)&sVh[n][kb + 8];
                Bl[0] = *(const uint32_t*)&sVl[n][kb];
                Bl[1] = *(const uint32_t*)&sVl[n][kb + 8];
#pragma unroll
                for (int im = 0; im < 2; im++) {
                    mma16816(acc[im][j], Ah2[im], Bh);
                    mma16816(acc[im][j], Al2[im], Bh);
                    mma16816(acc[im][j], Ah2[im], Bl);
                }
            }
        }
        __syncthreads();
    }

    // ---- epilogue: partials to g_part[ck][b] ----
    float* Pb = &g_part[ck][b][0][0];
#pragma unroll
    for (int im = 0; im < 2; im++) {
        int r = wm + im * 16 + gid;
#pragma unroll
        for (int j = 0; j < 8; j++) {
            int c = wn + j * 8 + tig * 2;
            *(float2*)&Pb[(size_t)r * DVn + c] =
                make_float2(acc[im][j][0], acc[im][j][1]);
            *(float2*)&Pb[(size_t)(r + 8) * DVn + c] =
                make_float2(acc[im][j][2], acc[im][j][3]);
        }
    }
}

// ---------------------------------------------------------------------------
// out = sum over 8 k-chunk partials. 256 CTAs x 256 threads x 1 float4.
// ---------------------------------------------------------------------------
__global__ void reduce_kernel(float* __restrict__ out) {
    const int idx = blockIdx.x * 256 + threadIdx.x;  // float4 index, 0..65535
    const float4* p = (const float4*)&g_part[0][0][0][0];
    const int stride = Bn * Qn * DVn / 4;  // 65536
    float4 s = p[idx];
#pragma unroll
    for (int c = 1; c < 8; c++) {
        float4 t = p[idx + c * stride];
        s.x += t.x; s.y += t.y; s.z += t.z; s.w += t.w;
    }
    ((float4*)out)[idx] = s;
}

// ---------------------------------------------------------------------------
extern "C" void kernel_launch(void* const* d_in, const int* in_sizes, int n_in,
                              void* d_out, int out_size) {
    const float* queries = (const float*)d_in[0];
    const float* keys    = (const float*)d_in[1];
    const float* values  = (const float*)d_in[2];
    const int*   vlens   = (const int*)d_in[3];
    const float* Wq      = (const float*)d_in[4];
    const float* Wk      = (const float*)d_in[5];
    const float* wv      = (const float*)d_in[6];
    float* out           = (float*)d_out;

    proj_mma_kernel<<<136, 256>>>(keys, queries, Wk, Wq);
    scores_kernel<<<dim3(Kn / 32, 2, Bn), 256>>>(wv);
    softmax_kernel<<<dim3(Qn, Bn), 256>>>(vlens);
    av_mma_kernel<<<dim3(8, Bn), 256>>>(values, vlens);
    reduce_kernel<<<256, 256>>>(out);
}